// round 14
// baseline (speedup 1.0000x reference)
#include <cuda_runtime.h>
#include <cuda_fp16.h>
#include <cstdint>
#include <math.h>

#define DD   64
#define HH   96
#define RR   3
#define VV   1024
#define CC   8
#define NMAX 400000
#define EMAX 2000000
#define GMAX 40000
#define NSEGMAX (NMAX * RR)
#define KDIM 384
#define AK   288                    // stored A columns (means only; self read from h1h)
#define NKSTEP (KDIM / 16)          // 24 mma k-steps (18 from A, 6 from h1h)
#define NNT 12                      // 96/8 n-tiles
#define STRIPE 65536                // nodes per layer-2 stripe (A stripe = 37.7MB, L2-resident)
#define SCAN_BLK 2048
#define NBMAX ((NSEGMAX + SCAN_BLK - 1) / SCAN_BLK)

// ---------------- static scratch (no runtime allocation) -----------------
__device__ __align__(16) int   g_cnt[NSEGMAX];          // zeroed-at-rest invariant
__device__ __align__(16) int   g_off[NSEGMAX + 1];
__device__ __align__(16) int   g_cur[NSEGMAX];
__device__ __align__(16) float g_inv[NSEGMAX];
__device__ __align__(16) int   g_esrc[EMAX];
__device__ __align__(16) unsigned long long g_desc[NBMAX]; // lookback descriptors, zeroed-at-rest
__device__ int g_ticket;                                    // zeroed-at-rest
__device__ __align__(16) float g_T1[RR * VV * HH];      // emb @ W1[r]
__device__ __align__(16) float g_T1r[VV * HH];          // emb @ root1 + b1
__device__ __align__(16) uint2 g_Wfrag[NKSTEP * NNT * 32]; // fp16 B fragments (per-thread packed)
__device__ __align__(16) __half g_h1h[(size_t)NMAX * HH];  // h1 fp16 (L2-resident)
__device__ __align__(16) __half g_A[(size_t)STRIPE * AK];  // layer-2 A stripe buffer (37.7MB, reused)
__device__ __align__(16) float g_gacc[GMAX * CC];       // zeroed-at-rest invariant
__device__ __align__(16) float g_gcnt[GMAX];            // zeroed-at-rest invariant

// ---------------- kernel 1: histogram + tables ----------------------------
__global__ void hist_tables_kernel(const int* __restrict__ ei, const int* __restrict__ et,
                                   const int* __restrict__ batch, int E, int N,
                                   int histBlocks,
                                   const float* __restrict__ emb, const float* __restrict__ W1,
                                   const float* __restrict__ root1, const float* __restrict__ b1,
                                   const float* __restrict__ W2, const float* __restrict__ root2,
                                   int Vr) {
    if (blockIdx.x < histBlocks) {
        int i = blockIdx.x * blockDim.x + threadIdx.x;
        if (i < E) {
            int d = ei[E + i];
            int r = et[i];
            atomicAdd(&g_cnt[d * RR + r], 1);
        }
        if (i < N) atomicAdd(&g_gcnt[batch[i]], 1.0f);
        return;
    }
    int idx = (blockIdx.x - histBlocks) * blockDim.x + threadIdx.x;
    int total1 = (RR + 1) * Vr * HH;
    if (idx < total1) {
        int h = idx % HH;
        int v = (idx / HH) % Vr;
        int t = idx / (HH * Vr);
        const float* erow = emb + v * DD;
        float s = 0.f;
        if (t < RR) {
            const float* w = W1 + (size_t)t * DD * HH;
            #pragma unroll
            for (int d = 0; d < DD; d++) s += erow[d] * w[d * HH + h];
            g_T1[((size_t)t * VV + v) * HH + h] = s;
        } else {
            #pragma unroll
            for (int d = 0; d < DD; d++) s += erow[d] * root1[d * HH + h];
            g_T1r[(size_t)v * HH + h] = s + b1[h];
        }
        return;
    }
    // pack layer-2 weights into per-thread mma B fragments (fp16)
    int j = idx - total1;
    if (j < NKSTEP * NNT * 32) {
        int t   = j & 31;
        int nt  = (j >> 5) % NNT;
        int ks  = (j >> 5) / NNT;
        int g   = t >> 2;
        int ti  = t & 3;
        int n   = nt * 8 + g;
        int k0  = ks * 16 + ti * 2;
        #define WK(K) ((K) < RR * HH ? W2[(K) * HH + n] : root2[((K) - RR * HH) * HH + n])
        __half2 b0 = __floats2half2_rn(WK(k0),     WK(k0 + 1));
        __half2 b1v = __floats2half2_rn(WK(k0 + 8), WK(k0 + 9));
        #undef WK
        uint2 u;
        u.x = *(unsigned int*)&b0;
        u.y = *(unsigned int*)&b1v;
        g_Wfrag[j] = u;
    }
}

// ---------------- kernel 2: single-pass scan (decoupled lookback) --------
__global__ void scan_kernel(int nseg, int E) {
    __shared__ int sh[256];
    __shared__ int s_vid;
    __shared__ unsigned int s_prefix;
    int tid = threadIdx.x;
    if (tid == 0) s_vid = atomicAdd(&g_ticket, 1);
    __syncthreads();
    int vid = s_vid;
    int base = vid * SCAN_BLK + tid * 8;
    int c[8], loc[8];
    int s = 0;
    #pragma unroll
    for (int i = 0; i < 8; i++) {
        int idx = base + i;
        c[i] = (idx < nseg) ? g_cnt[idx] : 0;
        loc[i] = s;
        s += c[i];
    }
    sh[tid] = s;
    __syncthreads();
    for (int o = 1; o < 256; o <<= 1) {
        int t = (tid >= o) ? sh[tid - o] : 0;
        __syncthreads();
        sh[tid] += t;
        __syncthreads();
    }
    int total = sh[255];
    if (tid == 0) {
        atomicExch(&g_desc[vid], (1ULL << 32) | (unsigned)total);
        unsigned long long prefix = 0;
        int p = vid - 1;
        while (p >= 0) {
            unsigned long long d;
            do { d = atomicAdd(&g_desc[p], 0ULL); } while ((d >> 32) == 0ull);
            prefix += (unsigned)d;
            if ((d >> 32) == 2ull) break;
            p--;
        }
        s_prefix = (unsigned)prefix;
        atomicExch(&g_desc[vid], (2ULL << 32) | (unsigned)(prefix + (unsigned)total));
    }
    __syncthreads();
    int toff = (int)s_prefix + sh[tid] - s;
    #pragma unroll
    for (int i = 0; i < 8; i++) {
        int idx = base + i;
        if (idx < nseg) {
            int o = toff + loc[i];
            g_off[idx] = o;
            g_cur[idx] = o;
            g_inv[idx] = 1.0f / ((c[i] > 0) ? (float)c[i] : 1.0f);
            g_cnt[idx] = 0;   // restore zeroed-at-rest
        }
    }
    if (vid == 0 && tid == 0) g_off[nseg] = E;
}

// ---------------- kernel 3: fill CSR --------------------------------------
__global__ void fill_kernel(const int* __restrict__ ei, const int* __restrict__ et, int E) {
    int e = blockIdx.x * blockDim.x + threadIdx.x;
    if (e >= E) return;
    int s = ei[e];
    int d = ei[E + e];
    int r = et[e];
    int p = atomicAdd(&g_cur[d * RR + r], 1);
    g_esrc[p] = s;
}

// ---------------- kernel 4: layer 1 (warp per node, table gather) --------
__global__ void layer1_kernel(const int* __restrict__ tokens, int N) {
    int warp = (blockIdx.x * blockDim.x + threadIdx.x) >> 5;
    int lane = threadIdx.x & 31;
    if (warp >= N) return;
    int n = warp;
    int o0 = g_off[n * RR], o1 = g_off[n * RR + 1], o2 = g_off[n * RR + 2], o3 = g_off[n * RR + 3];
    float a0[3] = {0.f, 0.f, 0.f}, a1[3] = {0.f, 0.f, 0.f}, a2[3] = {0.f, 0.f, 0.f};
    for (int base = o0; base < o3; base += 32) {
        int idx = base + lane;
        int tok = 0, r = 0;
        if (idx < o3) {
            int s = __ldcg(&g_esrc[idx]);
            tok = tokens[s];
            r = (idx >= o1) + (idx >= o2);
        }
        int m = o3 - base; if (m > 32) m = 32;
        for (int j = 0; j < m; j++) {
            int t  = __shfl_sync(0xffffffffu, tok, j);
            int rr = __shfl_sync(0xffffffffu, r, j);
            const float* row = g_T1 + ((size_t)rr * VV + t) * HH;
            float v0 = row[lane], v1 = row[lane + 32], v2 = row[lane + 64];
            if (rr == 0)      { a0[0] += v0; a0[1] += v1; a0[2] += v2; }
            else if (rr == 1) { a1[0] += v0; a1[1] += v1; a1[2] += v2; }
            else              { a2[0] += v0; a2[1] += v1; a2[2] += v2; }
        }
    }
    float i0 = g_inv[n * RR], i1 = g_inv[n * RR + 1], i2 = g_inv[n * RR + 2];
    int tn = tokens[n];
    const float* rt = g_T1r + (size_t)tn * HH;
    __half* hp = g_h1h + (size_t)n * HH;
    hp[lane]      = __float2half(fmaxf(a0[0] * i0 + a1[0] * i1 + a2[0] * i2 + rt[lane],      0.f));
    hp[lane + 32] = __float2half(fmaxf(a0[1] * i0 + a1[1] * i1 + a2[1] * i2 + rt[lane + 32], 0.f));
    hp[lane + 64] = __float2half(fmaxf(a0[2] * i0 + a1[2] * i1 + a2[2] * i2 + rt[lane + 64], 0.f));
}

// ---------------- kernel 5: layer-2 gather -> A stripe fp16 (288 cols) ---
__global__ void gather2_kernel(int n0, int n1) {
    int warp = (blockIdx.x * blockDim.x + threadIdx.x) >> 5;
    int lane = threadIdx.x & 31;
    int n = n0 + warp;
    if (n >= n1) return;
    float A[3][3] = {{0.f,0.f,0.f},{0.f,0.f,0.f},{0.f,0.f,0.f}};
    int o0 = g_off[n * RR], o1 = g_off[n * RR + 1], o2 = g_off[n * RR + 2], o3 = g_off[n * RR + 3];
    for (int base = o0; base < o3; base += 32) {
        int idx = base + lane;
        int s = 0, r = 0;
        if (idx < o3) {
            s = __ldcg(&g_esrc[idx]);
            r = (idx >= o1) + (idx >= o2);
        }
        int m = o3 - base; if (m > 32) m = 32;
        for (int j = 0; j < m; j++) {
            int ss = __shfl_sync(0xffffffffu, s, j);
            int rr = __shfl_sync(0xffffffffu, r, j);
            const __half* row = g_h1h + (size_t)ss * HH;
            float v0 = __half2float(row[lane]);
            float v1 = __half2float(row[lane + 32]);
            float v2 = __half2float(row[lane + 64]);
            if (rr == 0)      { A[0][0] += v0; A[0][1] += v1; A[0][2] += v2; }
            else if (rr == 1) { A[1][0] += v0; A[1][1] += v1; A[1][2] += v2; }
            else              { A[2][0] += v0; A[2][1] += v1; A[2][2] += v2; }
        }
    }
    float iv[3] = { g_inv[n * RR], g_inv[n * RR + 1], g_inv[n * RR + 2] };
    __half* ap = g_A + (size_t)(n - n0) * AK;
    #pragma unroll
    for (int r = 0; r < 3; r++)
        #pragma unroll
        for (int q = 0; q < 3; q++)
            ap[r * HH + q * 32 + lane] = __float2half(A[r][q] * iv[r]);
}

// ---------------- kernel 6: HMMA GEMM + relu + head + graph acc (stripe) -
#define MMA16816(D, A0, A1, A2, A3, B0, B1) \
    asm volatile("mma.sync.aligned.m16n8k16.row.col.f32.f16.f16.f32 " \
        "{%0,%1,%2,%3}, {%4,%5,%6,%7}, {%8,%9}, {%0,%1,%2,%3};" \
        : "+f"((D)[0]), "+f"((D)[1]), "+f"((D)[2]), "+f"((D)[3]) \
        : "r"(A0), "r"(A1), "r"(A2), "r"(A3), "r"(B0), "r"(B1))

__global__ void __launch_bounds__(256, 2)
gemm2_kernel(const float* __restrict__ b2, const float* __restrict__ linW,
             const int* __restrict__ batch, int n0, int n1) {
    extern __shared__ float smem[];
    float* sH2 = smem;                   // [128][100] (padded stride vs bank conflicts)
    float* sB2 = sH2 + 128 * 100;        // [96]
    float* sLW = sB2 + HH;               // [96*8]

    int tid = threadIdx.x;
    int lane = tid & 31;
    int w = tid >> 5;                    // 8 warps
    int groupID = lane >> 2;
    int tIG = lane & 3;

    for (int i = tid; i < HH;      i += 256) sB2[i] = b2[i];
    for (int i = tid; i < HH * CC; i += 256) sLW[i] = linW[i];

    int nblk = n0 + blockIdx.x * 128;
    int mwarp = (w & 3) * 32;            // warp M offset (4 warps x 32 rows)
    int nh = w >> 2;                     // 0/1: which 48-col half

    float d[2][6][4];
    #pragma unroll
    for (int mt = 0; mt < 2; mt++)
        #pragma unroll
        for (int nt = 0; nt < 6; nt++)
            #pragma unroll
            for (int q = 0; q < 4; q++) d[mt][nt][q] = 0.f;

    // row indices for A fragments (clamped within stripe; clamped rows discarded)
    int nclamp = n1 - 1;
    const __half* pA0[2];
    const __half* pA1[2];
    const __half* pH0[2];
    const __half* pH1[2];
    #pragma unroll
    for (int mt = 0; mt < 2; mt++) {
        int ra = nblk + mwarp + mt * 16 + groupID;
        int rb = ra + 8;
        if (ra > nclamp) ra = nclamp;
        if (rb > nclamp) rb = nclamp;
        pA0[mt] = g_A + (size_t)(ra - n0) * AK;
        pA1[mt] = g_A + (size_t)(rb - n0) * AK;
        pH0[mt] = g_h1h + (size_t)ra * HH;
        pH1[mt] = g_h1h + (size_t)rb * HH;
    }

    const uint2* wf = g_Wfrag + (size_t)nh * 6 * 32 + lane;

    // k-steps 0..17: means from A stripe (L2-resident)
    #pragma unroll 2
    for (int ks = 0; ks < 18; ks++) {
        int kc = ks * 16 + tIG * 2;
        unsigned int a[2][4];
        #pragma unroll
        for (int mt = 0; mt < 2; mt++) {
            a[mt][0] = *(const unsigned int*)(pA0[mt] + kc);
            a[mt][1] = *(const unsigned int*)(pA1[mt] + kc);
            a[mt][2] = *(const unsigned int*)(pA0[mt] + kc + 8);
            a[mt][3] = *(const unsigned int*)(pA1[mt] + kc + 8);
        }
        #pragma unroll
        for (int nt = 0; nt < 6; nt++) {
            uint2 b = wf[(ks * NNT + nt) * 32];
            MMA16816(d[0][nt], a[0][0], a[0][1], a[0][2], a[0][3], b.x, b.y);
            MMA16816(d[1][nt], a[1][0], a[1][1], a[1][2], a[1][3], b.x, b.y);
        }
    }
    // k-steps 18..23: self block directly from h1h (L2-resident)
    #pragma unroll
    for (int ks = 18; ks < NKSTEP; ks++) {
        int kc = ks * 16 + tIG * 2 - 288;
        unsigned int a[2][4];
        #pragma unroll
        for (int mt = 0; mt < 2; mt++) {
            a[mt][0] = *(const unsigned int*)(pH0[mt] + kc);
            a[mt][1] = *(const unsigned int*)(pH1[mt] + kc);
            a[mt][2] = *(const unsigned int*)(pH0[mt] + kc + 8);
            a[mt][3] = *(const unsigned int*)(pH1[mt] + kc + 8);
        }
        #pragma unroll
        for (int nt = 0; nt < 6; nt++) {
            uint2 b = wf[(ks * NNT + nt) * 32];
            MMA16816(d[0][nt], a[0][0], a[0][1], a[0][2], a[0][3], b.x, b.y);
            MMA16816(d[1][nt], a[1][0], a[1][1], a[1][2], a[1][3], b.x, b.y);
        }
    }
    __syncthreads();   // sB2/sLW ready; sH2 about to be written

    // epilogue: +b2, relu -> sH2
    #pragma unroll
    for (int mt = 0; mt < 2; mt++) {
        int rl0 = mwarp + mt * 16 + groupID;
        int rl1 = rl0 + 8;
        #pragma unroll
        for (int nt = 0; nt < 6; nt++) {
            int c0 = nh * 48 + nt * 8 + tIG * 2;
            sH2[rl0 * 100 + c0]     = fmaxf(d[mt][nt][0] + sB2[c0],     0.f);
            sH2[rl0 * 100 + c0 + 1] = fmaxf(d[mt][nt][1] + sB2[c0 + 1], 0.f);
            sH2[rl1 * 100 + c0]     = fmaxf(d[mt][nt][2] + sB2[c0],     0.f);
            sH2[rl1 * 100 + c0 + 1] = fmaxf(d[mt][nt][3] + sB2[c0 + 1], 0.f);
        }
    }
    __syncthreads();

    // classifier head + per-graph accumulation
    for (int u = tid; u < 128 * CC; u += 256) {
        int nl = u >> 3;
        int c = u & 7;
        int n = nblk + nl;
        if (n < n1) {
            float s = 0.f;
            #pragma unroll
            for (int h = 0; h < HH; h++) s += sH2[nl * 100 + h] * sLW[h * CC + c];
            atomicAdd(&g_gacc[batch[n] * CC + c], s);
        }
    }
}

// ---------------- kernel 7: finalize + reset all replay state -------------
__global__ void final_kernel(const float* __restrict__ linb, float* __restrict__ out,
                             int G, int nb) {
    int idx = blockIdx.x * blockDim.x + threadIdx.x;
    if (idx < nb) g_desc[idx] = 0ull;
    if (idx == 0) g_ticket = 0;
    if (idx >= G * CC) return;
    int g = idx / CC;
    int c = idx - g * CC;
    float acc = g_gacc[idx];
    float cnt = g_gcnt[g];
    out[idx] = acc / fmaxf(cnt, 1.0f) + linb[c];
    g_gacc[idx] = 0.f;
    __syncwarp();
    if (c == 0) g_gcnt[g] = 0.f;
}

// ---------------- launch --------------------------------------------------

extern "C" void kernel_launch(void* const* d_in, const int* in_sizes, int n_in,
                              void* d_out, int out_size) {
    const int* tokens = (const int*)d_in[0];
    const int* ei     = (const int*)d_in[1];
    const int* et     = (const int*)d_in[2];
    const int* batch  = (const int*)d_in[3];
    const float* emb   = (const float*)d_in[n_in - 9];
    const float* W1    = (const float*)d_in[n_in - 8];
    const float* root1 = (const float*)d_in[n_in - 7];
    const float* b1    = (const float*)d_in[n_in - 6];
    const float* W2    = (const float*)d_in[n_in - 5];
    const float* root2 = (const float*)d_in[n_in - 4];
    const float* b2    = (const float*)d_in[n_in - 3];
    const float* linW  = (const float*)d_in[n_in - 2];
    const float* linb  = (const float*)d_in[n_in - 1];
    float* out = (float*)d_out;

    int N = in_sizes[0];
    int E = in_sizes[2];
    int G = out_size / CC;
    int Vr = in_sizes[n_in - 9] / DD;
    int nseg = N * RR;
    int nb = (nseg + SCAN_BLK - 1) / SCAN_BLK;

    // 1) histogram + tables + weight-fragment packing
    {
        int mx = E > N ? E : N;
        int histBlocks = (mx + 255) / 256;
        int tabBlocks = ((RR + 1) * Vr * HH + NKSTEP * NNT * 32 + 255) / 256;
        hist_tables_kernel<<<histBlocks + tabBlocks, 256>>>(
            ei, et, batch, E, N, histBlocks, emb, W1, root1, b1, W2, root2, Vr);
    }
    // 2) single-pass scan (resets g_cnt)
    scan_kernel<<<nb, 256>>>(nseg, E);
    // 3) fill CSR
    fill_kernel<<<(E + 255) / 256, 256>>>(ei, et, E);
    // 4) layer 1 (warp per node; writes fp16 h1)
    layer1_kernel<<<(N + 7) / 8, 256>>>(tokens, N);
    // 5+6) layer 2 in stripes: gather to L2-resident A stripe, then GEMM
    {
        int smemBytes = (128 * 100 + HH + HH * CC) * (int)sizeof(float);
        cudaFuncSetAttribute(gemm2_kernel, cudaFuncAttributeMaxDynamicSharedMemorySize, smemBytes);
        for (int n0 = 0; n0 < N; n0 += STRIPE) {
            int n1 = n0 + STRIPE < N ? n0 + STRIPE : N;
            int sn = n1 - n0;
            gather2_kernel<<<(sn + 7) / 8, 256>>>(n0, n1);
            gemm2_kernel<<<(sn + 127) / 128, 256, smemBytes>>>(b2, linW, batch, n0, n1);
        }
    }
    // 7) finalize (+reset accumulators and scan state)
    final_kernel<<<(G * CC + 255) / 256, 256>>>(linb, out, G, nb);
}

// round 15
// speedup vs baseline: 1.1834x; 1.1834x over previous
#include <cuda_runtime.h>
#include <cuda_fp16.h>
#include <cstdint>
#include <math.h>

#define DD   64
#define HH   96
#define RR   3
#define VV   1024
#define CC   8
#define NMAX 400000
#define EMAX 2000000
#define GMAX 40000
#define NSEGMAX (NMAX * RR)
#define KDIM 384
#define AK   288                    // stored A columns (means only; self read from h1h)
#define NKSTEP (KDIM / 16)          // 24 mma k-steps (18 from A, 6 from h1h)
#define NNT 12                      // 96/8 n-tiles
#define SCAN_BLK 2048
#define NBMAX ((NSEGMAX + SCAN_BLK - 1) / SCAN_BLK)

// ---------------- static scratch (no runtime allocation) -----------------
__device__ __align__(16) int   g_cnt[NSEGMAX];          // zeroed-at-rest invariant
__device__ __align__(16) int   g_off[NSEGMAX + 1];
__device__ __align__(16) int   g_cur[NSEGMAX];
__device__ __align__(16) float g_inv[NSEGMAX];
__device__ __align__(16) int   g_esrc[EMAX];
__device__ __align__(16) unsigned long long g_desc[NBMAX]; // lookback descriptors, zeroed-at-rest
__device__ int g_ticket;                                    // zeroed-at-rest
__device__ __align__(16) float g_T1[RR * VV * HH];      // emb @ W1[r]
__device__ __align__(16) float g_T1r[VV * HH];          // emb @ root1 + b1
__device__ __align__(16) uint2 g_Wfrag[NKSTEP * NNT * 32]; // fp16 B fragments (per-thread packed)
__device__ __align__(16) __half g_h1h[(size_t)NMAX * HH];  // h1 fp16 (L2-resident)
__device__ __align__(16) __half g_A[(size_t)NMAX * AK];    // layer-2 A means (230MB)
__device__ __align__(16) float g_gacc[GMAX * CC];       // zeroed-at-rest invariant
__device__ __align__(16) float g_gcnt[GMAX];            // zeroed-at-rest invariant

// ---------------- kernel 1: histogram + tables ----------------------------
__global__ void hist_tables_kernel(const int* __restrict__ ei, const int* __restrict__ et,
                                   const int* __restrict__ batch, int E, int N,
                                   int histBlocks,
                                   const float* __restrict__ emb, const float* __restrict__ W1,
                                   const float* __restrict__ root1, const float* __restrict__ b1,
                                   const float* __restrict__ W2, const float* __restrict__ root2,
                                   int Vr) {
    if (blockIdx.x < histBlocks) {
        int i = blockIdx.x * blockDim.x + threadIdx.x;
        if (i < E) {
            int d = ei[E + i];
            int r = et[i];
            atomicAdd(&g_cnt[d * RR + r], 1);
        }
        if (i < N) atomicAdd(&g_gcnt[batch[i]], 1.0f);
        return;
    }
    int idx = (blockIdx.x - histBlocks) * blockDim.x + threadIdx.x;
    int total1 = (RR + 1) * Vr * HH;
    if (idx < total1) {
        int h = idx % HH;
        int v = (idx / HH) % Vr;
        int t = idx / (HH * Vr);
        const float* erow = emb + v * DD;
        float s = 0.f;
        if (t < RR) {
            const float* w = W1 + (size_t)t * DD * HH;
            #pragma unroll
            for (int d = 0; d < DD; d++) s += erow[d] * w[d * HH + h];
            g_T1[((size_t)t * VV + v) * HH + h] = s;
        } else {
            #pragma unroll
            for (int d = 0; d < DD; d++) s += erow[d] * root1[d * HH + h];
            g_T1r[(size_t)v * HH + h] = s + b1[h];
        }
        return;
    }
    // pack layer-2 weights into per-thread mma B fragments (fp16)
    int j = idx - total1;
    if (j < NKSTEP * NNT * 32) {
        int t   = j & 31;
        int nt  = (j >> 5) % NNT;
        int ks  = (j >> 5) / NNT;
        int g   = t >> 2;
        int ti  = t & 3;
        int n   = nt * 8 + g;
        int k0  = ks * 16 + ti * 2;
        #define WK(K) ((K) < RR * HH ? W2[(K) * HH + n] : root2[((K) - RR * HH) * HH + n])
        __half2 b0 = __floats2half2_rn(WK(k0),     WK(k0 + 1));
        __half2 b1v = __floats2half2_rn(WK(k0 + 8), WK(k0 + 9));
        #undef WK
        uint2 u;
        u.x = *(unsigned int*)&b0;
        u.y = *(unsigned int*)&b1v;
        g_Wfrag[j] = u;
    }
}

// ---------------- kernel 2: single-pass scan (decoupled lookback) --------
__global__ void scan_kernel(int nseg, int E) {
    __shared__ int sh[256];
    __shared__ int s_vid;
    __shared__ unsigned int s_prefix;
    int tid = threadIdx.x;
    if (tid == 0) s_vid = atomicAdd(&g_ticket, 1);
    __syncthreads();
    int vid = s_vid;
    int base = vid * SCAN_BLK + tid * 8;
    int c[8], loc[8];
    int s = 0;
    #pragma unroll
    for (int i = 0; i < 8; i++) {
        int idx = base + i;
        c[i] = (idx < nseg) ? g_cnt[idx] : 0;
        loc[i] = s;
        s += c[i];
    }
    sh[tid] = s;
    __syncthreads();
    for (int o = 1; o < 256; o <<= 1) {
        int t = (tid >= o) ? sh[tid - o] : 0;
        __syncthreads();
        sh[tid] += t;
        __syncthreads();
    }
    int total = sh[255];
    if (tid == 0) {
        atomicExch(&g_desc[vid], (1ULL << 32) | (unsigned)total);
        unsigned long long prefix = 0;
        int p = vid - 1;
        while (p >= 0) {
            unsigned long long d;
            do { d = atomicAdd(&g_desc[p], 0ULL); } while ((d >> 32) == 0ull);
            prefix += (unsigned)d;
            if ((d >> 32) == 2ull) break;
            p--;
        }
        s_prefix = (unsigned)prefix;
        atomicExch(&g_desc[vid], (2ULL << 32) | (unsigned)(prefix + (unsigned)total));
    }
    __syncthreads();
    int toff = (int)s_prefix + sh[tid] - s;
    #pragma unroll
    for (int i = 0; i < 8; i++) {
        int idx = base + i;
        if (idx < nseg) {
            int o = toff + loc[i];
            g_off[idx] = o;
            g_cur[idx] = o;
            g_inv[idx] = 1.0f / ((c[i] > 0) ? (float)c[i] : 1.0f);
            g_cnt[idx] = 0;   // restore zeroed-at-rest
        }
    }
    if (vid == 0 && tid == 0) g_off[nseg] = E;
}

// ---------------- kernel 3: fill CSR --------------------------------------
__global__ void fill_kernel(const int* __restrict__ ei, const int* __restrict__ et, int E) {
    int e = blockIdx.x * blockDim.x + threadIdx.x;
    if (e >= E) return;
    int s = ei[e];
    int d = ei[E + e];
    int r = et[e];
    int p = atomicAdd(&g_cur[d * RR + r], 1);
    g_esrc[p] = s;
}

// ---------------- kernel 4: layer 1 (warp per node, 2-edge unrolled) -----
__global__ void layer1_kernel(const int* __restrict__ tokens, int N) {
    int warp = (blockIdx.x * blockDim.x + threadIdx.x) >> 5;
    int lane = threadIdx.x & 31;
    if (warp >= N) return;
    int n = warp;
    int o0 = g_off[n * RR], o1 = g_off[n * RR + 1], o2 = g_off[n * RR + 2], o3 = g_off[n * RR + 3];
    float a0[3] = {0.f, 0.f, 0.f}, a1[3] = {0.f, 0.f, 0.f}, a2[3] = {0.f, 0.f, 0.f};
    for (int base = o0; base < o3; base += 32) {
        int idx = base + lane;
        int pack = 0;
        if (idx < o3) {
            int s = __ldcg(&g_esrc[idx]);
            int r = (idx >= o1) + (idx >= o2);
            pack = tokens[s] | (r << 10);          // tok < 1024
        }
        int m = o3 - base; if (m > 32) m = 32;
        int j = 0;
        for (; j + 1 < m; j += 2) {
            int pA = __shfl_sync(0xffffffffu, pack, j);
            int pB = __shfl_sync(0xffffffffu, pack, j + 1);
            const float* rowA = g_T1 + ((size_t)(pA >> 10) * VV + (pA & 1023)) * HH;
            const float* rowB = g_T1 + ((size_t)(pB >> 10) * VV + (pB & 1023)) * HH;
            float uA0 = rowA[lane], uA1 = rowA[lane + 32], uA2 = rowA[lane + 64];
            float uB0 = rowB[lane], uB1 = rowB[lane + 32], uB2 = rowB[lane + 64];
            int rA = pA >> 10, rB = pB >> 10;
            if (rA == 0)      { a0[0] += uA0; a0[1] += uA1; a0[2] += uA2; }
            else if (rA == 1) { a1[0] += uA0; a1[1] += uA1; a1[2] += uA2; }
            else              { a2[0] += uA0; a2[1] += uA1; a2[2] += uA2; }
            if (rB == 0)      { a0[0] += uB0; a0[1] += uB1; a0[2] += uB2; }
            else if (rB == 1) { a1[0] += uB0; a1[1] += uB1; a1[2] += uB2; }
            else              { a2[0] += uB0; a2[1] += uB1; a2[2] += uB2; }
        }
        if (j < m) {
            int pA = __shfl_sync(0xffffffffu, pack, j);
            const float* rowA = g_T1 + ((size_t)(pA >> 10) * VV + (pA & 1023)) * HH;
            float uA0 = rowA[lane], uA1 = rowA[lane + 32], uA2 = rowA[lane + 64];
            int rA = pA >> 10;
            if (rA == 0)      { a0[0] += uA0; a0[1] += uA1; a0[2] += uA2; }
            else if (rA == 1) { a1[0] += uA0; a1[1] += uA1; a1[2] += uA2; }
            else              { a2[0] += uA0; a2[1] += uA1; a2[2] += uA2; }
        }
    }
    float i0 = g_inv[n * RR], i1 = g_inv[n * RR + 1], i2 = g_inv[n * RR + 2];
    int tn = tokens[n];
    const float* rt = g_T1r + (size_t)tn * HH;
    __half* hp = g_h1h + (size_t)n * HH;
    hp[lane]      = __float2half(fmaxf(a0[0] * i0 + a1[0] * i1 + a2[0] * i2 + rt[lane],      0.f));
    hp[lane + 32] = __float2half(fmaxf(a0[1] * i0 + a1[1] * i1 + a2[1] * i2 + rt[lane + 32], 0.f));
    hp[lane + 64] = __float2half(fmaxf(a0[2] * i0 + a1[2] * i1 + a2[2] * i2 + rt[lane + 64], 0.f));
}

// ---------------- kernel 5: layer-2 gather (2-edge unrolled) -> A fp16 ---
__global__ void gather2_kernel(int N) {
    int warp = (blockIdx.x * blockDim.x + threadIdx.x) >> 5;
    int lane = threadIdx.x & 31;
    if (warp >= N) return;
    int n = warp;
    float A[3][3] = {{0.f,0.f,0.f},{0.f,0.f,0.f},{0.f,0.f,0.f}};
    int o0 = g_off[n * RR], o1 = g_off[n * RR + 1], o2 = g_off[n * RR + 2], o3 = g_off[n * RR + 3];
    for (int base = o0; base < o3; base += 32) {
        int idx = base + lane;
        int pack = 0;
        if (idx < o3) {
            int s = __ldcg(&g_esrc[idx]);
            int r = (idx >= o1) + (idx >= o2);
            pack = s | (r << 19);                  // s < 2^19
        }
        int m = o3 - base; if (m > 32) m = 32;
        int j = 0;
        for (; j + 1 < m; j += 2) {
            int pA = __shfl_sync(0xffffffffu, pack, j);
            int pB = __shfl_sync(0xffffffffu, pack, j + 1);
            const __half* rowA = g_h1h + (size_t)(pA & 0x7FFFF) * HH;
            const __half* rowB = g_h1h + (size_t)(pB & 0x7FFFF) * HH;
            float uA0 = __half2float(rowA[lane]);
            float uA1 = __half2float(rowA[lane + 32]);
            float uA2 = __half2float(rowA[lane + 64]);
            float uB0 = __half2float(rowB[lane]);
            float uB1 = __half2float(rowB[lane + 32]);
            float uB2 = __half2float(rowB[lane + 64]);
            int rA = pA >> 19, rB = pB >> 19;
            if (rA == 0)      { A[0][0] += uA0; A[0][1] += uA1; A[0][2] += uA2; }
            else if (rA == 1) { A[1][0] += uA0; A[1][1] += uA1; A[1][2] += uA2; }
            else              { A[2][0] += uA0; A[2][1] += uA1; A[2][2] += uA2; }
            if (rB == 0)      { A[0][0] += uB0; A[0][1] += uB1; A[0][2] += uB2; }
            else if (rB == 1) { A[1][0] += uB0; A[1][1] += uB1; A[1][2] += uB2; }
            else              { A[2][0] += uB0; A[2][1] += uB1; A[2][2] += uB2; }
        }
        if (j < m) {
            int pA = __shfl_sync(0xffffffffu, pack, j);
            const __half* rowA = g_h1h + (size_t)(pA & 0x7FFFF) * HH;
            float uA0 = __half2float(rowA[lane]);
            float uA1 = __half2float(rowA[lane + 32]);
            float uA2 = __half2float(rowA[lane + 64]);
            int rA = pA >> 19;
            if (rA == 0)      { A[0][0] += uA0; A[0][1] += uA1; A[0][2] += uA2; }
            else if (rA == 1) { A[1][0] += uA0; A[1][1] += uA1; A[1][2] += uA2; }
            else              { A[2][0] += uA0; A[2][1] += uA1; A[2][2] += uA2; }
        }
    }
    float iv[3] = { g_inv[n * RR], g_inv[n * RR + 1], g_inv[n * RR + 2] };
    __half* ap = g_A + (size_t)n * AK;
    #pragma unroll
    for (int r = 0; r < 3; r++)
        #pragma unroll
        for (int q = 0; q < 3; q++)
            ap[r * HH + q * 32 + lane] = __float2half(A[r][q] * iv[r]);
    // no self copy: gemm2 reads self block directly from g_h1h
}

// ---------------- kernel 6: HMMA GEMM + relu + head + graph acc ----------
#define MMA16816(D, A0, A1, A2, A3, B0, B1) \
    asm volatile("mma.sync.aligned.m16n8k16.row.col.f32.f16.f16.f32 " \
        "{%0,%1,%2,%3}, {%4,%5,%6,%7}, {%8,%9}, {%0,%1,%2,%3};" \
        : "+f"((D)[0]), "+f"((D)[1]), "+f"((D)[2]), "+f"((D)[3]) \
        : "r"(A0), "r"(A1), "r"(A2), "r"(A3), "r"(B0), "r"(B1))

__global__ void __launch_bounds__(256, 2)
gemm2_kernel(const float* __restrict__ b2, const float* __restrict__ linW,
             const int* __restrict__ batch, int N) {
    extern __shared__ float smem[];
    float* sH2 = smem;                   // [128][100] (padded stride vs bank conflicts)
    float* sB2 = sH2 + 128 * 100;        // [96]
    float* sLW = sB2 + HH;               // [96*8]

    int tid = threadIdx.x;
    int lane = tid & 31;
    int w = tid >> 5;                    // 8 warps
    int groupID = lane >> 2;
    int tIG = lane & 3;

    for (int i = tid; i < HH;      i += 256) sB2[i] = b2[i];
    for (int i = tid; i < HH * CC; i += 256) sLW[i] = linW[i];

    int n0 = blockIdx.x * 128;
    int mwarp = (w & 3) * 32;            // warp M offset (4 warps x 32 rows)
    int nh = w >> 2;                     // 0/1: which 48-col half

    float d[2][6][4];
    #pragma unroll
    for (int mt = 0; mt < 2; mt++)
        #pragma unroll
        for (int nt = 0; nt < 6; nt++)
            #pragma unroll
            for (int q = 0; q < 4; q++) d[mt][nt][q] = 0.f;

    // row indices for A fragments (clamped; clamped rows' outputs are discarded)
    int nclamp = N - 1;
    const __half* pA0[2];
    const __half* pA1[2];
    const __half* pH0[2];
    const __half* pH1[2];
    #pragma unroll
    for (int mt = 0; mt < 2; mt++) {
        int ra = n0 + mwarp + mt * 16 + groupID;
        int rb = ra + 8;
        if (ra > nclamp) ra = nclamp;
        if (rb > nclamp) rb = nclamp;
        pA0[mt] = g_A + (size_t)ra * AK;
        pA1[mt] = g_A + (size_t)rb * AK;
        pH0[mt] = g_h1h + (size_t)ra * HH;
        pH1[mt] = g_h1h + (size_t)rb * HH;
    }

    const uint2* wf = g_Wfrag + (size_t)nh * 6 * 32 + lane;

    // k-steps 0..17: means from A
    #pragma unroll 2
    for (int ks = 0; ks < 18; ks++) {
        int kc = ks * 16 + tIG * 2;
        unsigned int a[2][4];
        #pragma unroll
        for (int mt = 0; mt < 2; mt++) {
            a[mt][0] = *(const unsigned int*)(pA0[mt] + kc);
            a[mt][1] = *(const unsigned int*)(pA1[mt] + kc);
            a[mt][2] = *(const unsigned int*)(pA0[mt] + kc + 8);
            a[mt][3] = *(const unsigned int*)(pA1[mt] + kc + 8);
        }
        #pragma unroll
        for (int nt = 0; nt < 6; nt++) {
            uint2 b = wf[(ks * NNT + nt) * 32];
            MMA16816(d[0][nt], a[0][0], a[0][1], a[0][2], a[0][3], b.x, b.y);
            MMA16816(d[1][nt], a[1][0], a[1][1], a[1][2], a[1][3], b.x, b.y);
        }
    }
    // k-steps 18..23: self block directly from h1h (L2-resident)
    #pragma unroll
    for (int ks = 18; ks < NKSTEP; ks++) {
        int kc = ks * 16 + tIG * 2 - 288;
        unsigned int a[2][4];
        #pragma unroll
        for (int mt = 0; mt < 2; mt++) {
            a[mt][0] = *(const unsigned int*)(pH0[mt] + kc);
            a[mt][1] = *(const unsigned int*)(pH1[mt] + kc);
            a[mt][2] = *(const unsigned int*)(pH0[mt] + kc + 8);
            a[mt][3] = *(const unsigned int*)(pH1[mt] + kc + 8);
        }
        #pragma unroll
        for (int nt = 0; nt < 6; nt++) {
            uint2 b = wf[(ks * NNT + nt) * 32];
            MMA16816(d[0][nt], a[0][0], a[0][1], a[0][2], a[0][3], b.x, b.y);
            MMA16816(d[1][nt], a[1][0], a[1][1], a[1][2], a[1][3], b.x, b.y);
        }
    }
    __syncthreads();   // sB2/sLW ready; sH2 about to be written

    // epilogue: +b2, relu -> sH2
    #pragma unroll
    for (int mt = 0; mt < 2; mt++) {
        int rl0 = mwarp + mt * 16 + groupID;
        int rl1 = rl0 + 8;
        #pragma unroll
        for (int nt = 0; nt < 6; nt++) {
            int c0 = nh * 48 + nt * 8 + tIG * 2;
            sH2[rl0 * 100 + c0]     = fmaxf(d[mt][nt][0] + sB2[c0],     0.f);
            sH2[rl0 * 100 + c0 + 1] = fmaxf(d[mt][nt][1] + sB2[c0 + 1], 0.f);
            sH2[rl1 * 100 + c0]     = fmaxf(d[mt][nt][2] + sB2[c0],     0.f);
            sH2[rl1 * 100 + c0 + 1] = fmaxf(d[mt][nt][3] + sB2[c0 + 1], 0.f);
        }
    }
    __syncthreads();

    // classifier head + per-graph accumulation
    for (int u = tid; u < 128 * CC; u += 256) {
        int nl = u >> 3;
        int c = u & 7;
        int n = n0 + nl;
        if (n < N) {
            float s = 0.f;
            #pragma unroll
            for (int h = 0; h < HH; h++) s += sH2[nl * 100 + h] * sLW[h * CC + c];
            atomicAdd(&g_gacc[batch[n] * CC + c], s);
        }
    }
}

// ---------------- kernel 7: finalize + reset all replay state -------------
__global__ void final_kernel(const float* __restrict__ linb, float* __restrict__ out,
                             int G, int nb) {
    int idx = blockIdx.x * blockDim.x + threadIdx.x;
    if (idx < nb) g_desc[idx] = 0ull;
    if (idx == 0) g_ticket = 0;
    if (idx >= G * CC) return;
    int g = idx / CC;
    int c = idx - g * CC;
    float acc = g_gacc[idx];
    float cnt = g_gcnt[g];
    out[idx] = acc / fmaxf(cnt, 1.0f) + linb[c];
    g_gacc[idx] = 0.f;
    __syncwarp();
    if (c == 0) g_gcnt[g] = 0.f;
}

// ---------------- launch --------------------------------------------------

extern "C" void kernel_launch(void* const* d_in, const int* in_sizes, int n_in,
                              void* d_out, int out_size) {
    const int* tokens = (const int*)d_in[0];
    const int* ei     = (const int*)d_in[1];
    const int* et     = (const int*)d_in[2];
    const int* batch  = (const int*)d_in[3];
    const float* emb   = (const float*)d_in[n_in - 9];
    const float* W1    = (const float*)d_in[n_in - 8];
    const float* root1 = (const float*)d_in[n_in - 7];
    const float* b1    = (const float*)d_in[n_in - 6];
    const float* W2    = (const float*)d_in[n_in - 5];
    const float* root2 = (const float*)d_in[n_in - 4];
    const float* b2    = (const float*)d_in[n_in - 3];
    const float* linW  = (const float*)d_in[n_in - 2];
    const float* linb  = (const float*)d_in[n_in - 1];
    float* out = (float*)d_out;

    int N = in_sizes[0];
    int E = in_sizes[2];
    int G = out_size / CC;
    int Vr = in_sizes[n_in - 9] / DD;
    int nseg = N * RR;
    int nb = (nseg + SCAN_BLK - 1) / SCAN_BLK;

    // 1) histogram + tables + weight-fragment packing
    {
        int mx = E > N ? E : N;
        int histBlocks = (mx + 255) / 256;
        int tabBlocks = ((RR + 1) * Vr * HH + NKSTEP * NNT * 32 + 255) / 256;
        hist_tables_kernel<<<histBlocks + tabBlocks, 256>>>(
            ei, et, batch, E, N, histBlocks, emb, W1, root1, b1, W2, root2, Vr);
    }
    // 2) single-pass scan (resets g_cnt)
    scan_kernel<<<nb, 256>>>(nseg, E);
    // 3) fill CSR
    fill_kernel<<<(E + 255) / 256, 256>>>(ei, et, E);
    // 4) layer 1 (warp per node; 2-edge unrolled; writes fp16 h1)
    layer1_kernel<<<(N + 7) / 8, 256>>>(tokens, N);
    // 5) layer-2 gather -> A means fp16 (288 cols, 2-edge unrolled)
    gather2_kernel<<<(N + 7) / 8, 256>>>(N);
    // 6) layer-2 HMMA GEMM + head (self block read from h1h)
    {
        int smemBytes = (128 * 100 + HH + HH * CC) * (int)sizeof(float);
        cudaFuncSetAttribute(gemm2_kernel, cudaFuncAttributeMaxDynamicSharedMemorySize, smemBytes);
        int grid = (N + 127) / 128;
        gemm2_kernel<<<grid, 256, smemBytes>>>(b2, linW, batch, N);
    }
    // 7) finalize (+reset accumulators and scan state)
    final_kernel<<<(G * CC + 255) / 256, 256>>>(linb, out, G, nb);
}